// round 15
// baseline (speedup 1.0000x reference)
#include <cuda_runtime.h>
#include <cuda_bf16.h>
#include <math.h>

// ---------------------------------------------------------------------------
// AutoEncoder3D + symmetric Chamfer loss, 2-kernel pipeline with in-kernel
// global barriers (all blocks of each grid provably co-resident).
// B=2, D_IN=1024, SPACE=3, BOTT=64, G=64, N=G*1024=65536 per batch.
// ---------------------------------------------------------------------------

#define NEG_INF (__int_as_float(0xff800000))

typedef unsigned long long u64t;
__device__ __forceinline__ u64t pk2(float lo, float hi) {
    u64t r; asm("mov.b64 %0, {%1, %2};" : "=l"(r) : "f"(lo), "f"(hi)); return r;
}
__device__ __forceinline__ void upk2(float& lo, float& hi, u64t v) {
    asm("mov.b64 {%0, %1}, %2;" : "=f"(lo), "=f"(hi) : "l"(v));
}
__device__ __forceinline__ u64t fma2(u64t a, u64t b, u64t c) {
    u64t d; asm("fma.rn.f32x2 %0, %1, %2, %3;" : "=l"(d) : "l"(a), "l"(b), "l"(c)); return d;
}
__device__ __forceinline__ u64t add2(u64t a, u64t b) {
    u64t d; asm("add.rn.f32x2 %0, %1, %2;" : "=l"(d) : "l"(a), "l"(b)); return d;
}

// ---------------- scratch ----------------------------------------------------
__device__ float    g_h1part[16][2][512];
__device__ float    g_h2part[8][2][128];
__device__ float    g_d2t[512 * 128];        // dec L2 activations, transposed [k][row]
__device__ float    g_p3[8][128 * 3072];     // dec3 K-split partials
__device__ unsigned g_umax[2048];
__device__ float    g_partN[512];
__device__ unsigned g_done;
__device__ unsigned g_barA1, g_barA2, g_barB;   // global barrier counters

__device__ __forceinline__ unsigned enc_f(float f) {
    unsigned u = __float_as_uint(f);
    return (u & 0x80000000u) ? ~u : (u | 0x80000000u);
}
__device__ __forceinline__ float dec_f(unsigned u) {
    unsigned v = (u & 0x80000000u) ? (u & 0x7FFFFFFFu) : ~u;
    return __uint_as_float(v);
}

// counter global barrier; safe iff the whole grid is co-resident
__device__ __forceinline__ void gbar(unsigned* ctr, unsigned target) {
    __syncthreads();
    __threadfence();
    if (threadIdx.x == 0) {
        atomicAdd(ctr, 1u);
        while (*((volatile unsigned*)ctr) < target) {}
    }
    __syncthreads();
    __threadfence();
}

// ============================================================================
// Kernel A: encoder L1 (K-split x16) + L2 (K-split x8) + e3/dec12
// Grid 128 x 128 threads. 128 <= 148 SMs -> always co-resident.
// ============================================================================
__global__ void __launch_bounds__(128) k_enc(
    const float* __restrict__ x, const float* __restrict__ We1,
    const float* __restrict__ be1, const float* __restrict__ We2,
    const float* __restrict__ be2, const float* __restrict__ We3,
    const float* __restrict__ be3, const float* __restrict__ grid,
    const float* __restrict__ Wd1, const float* __restrict__ bd1,
    const float* __restrict__ Wd2, const float* __restrict__ bd2)
{
    __shared__ float sm[256];                    // xs(192) / h1c(64) / reused
    __shared__ float d1s[128];
    const int tid = threadIdx.x, bid = blockIdx.x;

    if (bid == 0) {                              // per-replay re-init
        for (int i = tid; i < 2048; i += 128) g_umax[i] = 0u;
        if (tid == 0) { g_done = 0u; g_barB = 0u; }
    }

    // ---- phase 1: e1. 128 blocks = 32 (b,kc) pairs x 4 col-chunks ----------
    {
        const int pair = bid >> 2, chunk = bid & 3;
        const int b = pair >> 4, kc = pair & 15;
        const int col = chunk * 128 + tid;
        for (int i = tid; i < 192; i += 128) sm[i] = x[b * 3072 + kc * 192 + i];
        __syncthreads();
        const float* W = We1 + (size_t)(kc * 192) * 512 + col;
        float a0 = 0.f, a1 = 0.f, a2 = 0.f, a3 = 0.f;
#pragma unroll 16
        for (int i = 0; i < 192; i += 4) {
            a0 = fmaf(sm[i + 0], W[(size_t)(i + 0) * 512], a0);
            a1 = fmaf(sm[i + 1], W[(size_t)(i + 1) * 512], a1);
            a2 = fmaf(sm[i + 2], W[(size_t)(i + 2) * 512], a2);
            a3 = fmaf(sm[i + 3], W[(size_t)(i + 3) * 512], a3);
        }
        g_h1part[kc][b][col] = (a0 + a1) + (a2 + a3);
    }
    gbar(&g_barA1, 128);

    // ---- phase 2: e2 on blocks 0..15 ---------------------------------------
    if (bid < 16) {
        const int b = bid >> 3, kc = bid & 7;
        if (tid < 64) {
            const int col = kc * 64 + tid;
            float a = be1[col];
#pragma unroll
            for (int p = 0; p < 16; p++) a += g_h1part[p][b][col];
            sm[tid] = fmaxf(a, 0.f);
        }
        __syncthreads();
        const float* W = We2 + (size_t)(kc * 64) * 128 + tid;
        float c0 = 0.f, c1 = 0.f, c2 = 0.f, c3 = 0.f;
#pragma unroll
        for (int k = 0; k < 64; k += 4) {
            c0 = fmaf(sm[k + 0], W[(size_t)(k + 0) * 128], c0);
            c1 = fmaf(sm[k + 1], W[(size_t)(k + 1) * 128], c1);
            c2 = fmaf(sm[k + 2], W[(size_t)(k + 2) * 128], c2);
            c3 = fmaf(sm[k + 3], W[(size_t)(k + 3) * 128], c3);
        }
        g_h2part[kc][b][tid] = (c0 + c1) + (c2 + c3);
    }
    gbar(&g_barA2, 128);

    // ---- phase 3: e3 + dec layers 1+2, one block per (b,g) -----------------
    {
        const int r = bid, b = r >> 6, g = r & 63;
        float* h2s = sm;                          // reuse [0..127]
        float* zi  = sm + 128;                    // [128..195] (68 used)
        {
            float a = be2[tid];
#pragma unroll
            for (int p = 0; p < 8; p++) a += g_h2part[p][b][tid];
            h2s[tid] = fmaxf(a, 0.f);
        }
        __syncthreads();
        if (tid < 64) {
            float a = be3[tid];
#pragma unroll 8
            for (int i = 0; i < 128; i++) a = fmaf(h2s[i], We3[(size_t)i * 64 + tid], a);
            zi[tid] = fmaxf(a, 0.f);
        } else if (tid < 67) {
            zi[tid] = grid[g * 3 + (tid - 64)];
        }
        __syncthreads();

        float a = bd1[tid];
#pragma unroll
        for (int i = 0; i < 67; i++) a = fmaf(zi[i], Wd1[(size_t)i * 128 + tid], a);
        d1s[tid] = fmaxf(a, 0.f);
        __syncthreads();

        float c0 = bd2[tid], c1 = bd2[tid + 128], c2 = bd2[tid + 256], c3 = bd2[tid + 384];
#pragma unroll 8
        for (int i = 0; i < 128; i++) {
            const float h = d1s[i];
            const float* W = Wd2 + (size_t)i * 512 + tid;
            c0 = fmaf(h, W[0],   c0);
            c1 = fmaf(h, W[128], c1);
            c2 = fmaf(h, W[256], c2);
            c3 = fmaf(h, W[384], c3);
        }
        g_d2t[(size_t)(tid)       * 128 + r] = fmaxf(c0, 0.f);
        g_d2t[(size_t)(tid + 128) * 128 + r] = fmaxf(c1, 0.f);
        g_d2t[(size_t)(tid + 256) * 128 + r] = fmaxf(c2, 0.f);
        g_d2t[(size_t)(tid + 384) * 128 + r] = fmaxf(c3, 0.f);
    }
}

// ============================================================================
// Kernel B: dec3 (768 blocks) -> global barrier -> chamfer (blocks 0..511)
// __launch_bounds__(128, 6): 6 blocks/SM guaranteed -> 888 slots >= 768,
// whole grid co-resident in wave 1 -> barrier is deadlock-free.
// ============================================================================
#define CH_NS 256
struct SmemB {
    union {
        struct { float As[32][132]; float Bs[32][32]; } d3;
        struct {
            float ys2[CH_NS][8];
            float ysc[CH_NS * 3];
            float mred[32][133];
            float pw2[32][4];
            float red2[4];
        } ch;
    };
};

__global__ void __launch_bounds__(128, 6) k_decch(
    const float* __restrict__ Wd3, const float* __restrict__ bd3,
    const float* __restrict__ x, float* __restrict__ out)
{
    __shared__ SmemB smb;
    __shared__ unsigned isLast;
    const int tid = threadIdx.x, bid = blockIdx.x;
    const int lane = tid & 31, w = tid >> 5;

    if (bid == 767 && tid == 0) { g_barA1 = 0u; g_barA2 = 0u; }  // for next replay

    // ---- phase 1: dec3 GEMM, 8-way K-split, row-pair FFMA2 -----------------
    {
        const int nt = bid % 96, kc = bid / 96;
        const int n0 = nt * 32, kbase = kc * 64;
        const int tx = tid & 7, ty = tid >> 3;

        u64t acc[4][4];
#pragma unroll
        for (int p = 0; p < 4; p++)
#pragma unroll
            for (int c = 0; c < 4; c++) acc[p][c] = 0ull;

        for (int ks = 0; ks < 64; ks += 32) {
#pragma unroll
            for (int j = 0; j < 8; j++) {
                const int idx = tid + j * 128;
                const int kk = idx >> 5, r4 = idx & 31;
                *(float4*)&smb.d3.As[kk][r4 * 4] =
                    *(const float4*)&g_d2t[(size_t)(kbase + ks + kk) * 128 + r4 * 4];
            }
#pragma unroll
            for (int j = 0; j < 2; j++) {
                const int idx = tid + j * 128;
                const int kk = idx >> 3, c4 = idx & 7;
                *(float4*)&smb.d3.Bs[kk][c4 * 4] =
                    *(const float4*)&Wd3[(size_t)(kbase + ks + kk) * 3072 + n0 + c4 * 4];
            }
            __syncthreads();
#pragma unroll
            for (int kk = 0; kk < 32; kk++) {
                const ulonglong2 aA = *(const ulonglong2*)&smb.d3.As[kk][ty * 8];
                const ulonglong2 aB = *(const ulonglong2*)&smb.d3.As[kk][ty * 8 + 4];
                const float4 bv = *(const float4*)&smb.d3.Bs[kk][tx * 4];
                const u64t b0 = pk2(bv.x, bv.x), b1 = pk2(bv.y, bv.y);
                const u64t b2 = pk2(bv.z, bv.z), b3 = pk2(bv.w, bv.w);
                acc[0][0] = fma2(aA.x, b0, acc[0][0]); acc[0][1] = fma2(aA.x, b1, acc[0][1]);
                acc[0][2] = fma2(aA.x, b2, acc[0][2]); acc[0][3] = fma2(aA.x, b3, acc[0][3]);
                acc[1][0] = fma2(aA.y, b0, acc[1][0]); acc[1][1] = fma2(aA.y, b1, acc[1][1]);
                acc[1][2] = fma2(aA.y, b2, acc[1][2]); acc[1][3] = fma2(aA.y, b3, acc[1][3]);
                acc[2][0] = fma2(aB.x, b0, acc[2][0]); acc[2][1] = fma2(aB.x, b1, acc[2][1]);
                acc[2][2] = fma2(aB.x, b2, acc[2][2]); acc[2][3] = fma2(aB.x, b3, acc[2][3]);
                acc[3][0] = fma2(aB.y, b0, acc[3][0]); acc[3][1] = fma2(aB.y, b1, acc[3][1]);
                acc[3][2] = fma2(aB.y, b2, acc[3][2]); acc[3][3] = fma2(aB.y, b3, acc[3][3]);
            }
            __syncthreads();
        }

        float* P = g_p3[kc];
#pragma unroll
        for (int p = 0; p < 4; p++) {
            float l0, h0, l1, h1, l2, h2, l3, h3;
            upk2(l0, h0, acc[p][0]);
            upk2(l1, h1, acc[p][1]);
            upk2(l2, h2, acc[p][2]);
            upk2(l3, h3, acc[p][3]);
            const int r0 = ty * 8 + 2 * p;
            *(float4*)&P[(size_t)r0 * 3072 + n0 + tx * 4]       = make_float4(l0, l1, l2, l3);
            *(float4*)&P[(size_t)(r0 + 1) * 3072 + n0 + tx * 4] = make_float4(h0, h1, h2, h3);
        }
    }

    gbar(&g_barB, 768);
    if (bid >= 512) return;

    // ---- phase 2: fused tanh + symmetric Chamfer ---------------------------
    const int b = bid >> 8, s = bid & 255;
    const int n0 = s * CH_NS;

    {
        const int gf0 = b * 196608 + n0 * 3;
        const int col0 = (n0 & 1023) * 3;
        for (int o4 = tid; o4 < 192; o4 += 128) {
            const int o = o4 * 4;
            float4 sacc = *(const float4*)&g_p3[0][gf0 + o];
#pragma unroll
            for (int p = 1; p < 8; p++) {
                const float4 q = *(const float4*)&g_p3[p][gf0 + o];
                sacc.x += q.x; sacc.y += q.y; sacc.z += q.z; sacc.w += q.w;
            }
            const float4 bb = *(const float4*)&bd3[col0 + o];
            sacc.x = tanhf(sacc.x + bb.x);
            sacc.y = tanhf(sacc.y + bb.y);
            sacc.z = tanhf(sacc.z + bb.z);
            sacc.w = tanhf(sacc.w + bb.w);
            *(float4*)&smb.ch.ysc[o] = sacc;
        }
    }
    __syncthreads();
    for (int nn = tid; nn < CH_NS; nn += 128) {
        const float yx = smb.ch.ysc[nn * 3 + 0];
        const float yy = smb.ch.ysc[nn * 3 + 1];
        const float yz = smb.ch.ysc[nn * 3 + 2];
        const float yw = -0.5f * (yx * yx + yy * yy + yz * yz);
        *(float4*)&smb.ch.ys2[nn][0] = make_float4(yx, yx, yy, yy);
        *(float4*)&smb.ch.ys2[nn][4] = make_float4(yz, yz, yw, yw);
    }

    u64t sx2[4], sy2[4], sz2[4], hs2[4];
    float mBlo[4], mBhi[4];
    const float* xb = x + (size_t)b * 3072;
#pragma unroll
    for (int g = 0; g < 4; g++) {
        const int m0 = w * 256 + (2 * g) * 32 + lane;
        const int m1 = m0 + 32;
        const float ax = xb[m0 * 3 + 0], ay = xb[m0 * 3 + 1], az = xb[m0 * 3 + 2];
        const float cx = xb[m1 * 3 + 0], cy = xb[m1 * 3 + 1], cz = xb[m1 * 3 + 2];
        sx2[g] = pk2(ax, cx);
        sy2[g] = pk2(ay, cy);
        sz2[g] = pk2(az, cz);
        hs2[g] = pk2(-0.5f * (ax * ax + ay * ay + az * az),
                     -0.5f * (cx * cx + cy * cy + cz * cz));
        mBlo[g] = NEG_INF; mBhi[g] = NEG_INF;
    }
    __syncthreads();

    float sum_n = 0.f;
    for (int c0 = 0; c0 < CH_NS; c0 += 32) {
#pragma unroll 2
        for (int k = 0; k < 32; k++) {
            const int nn = c0 + k;
            const ulonglong2 yA = *(const ulonglong2*)&smb.ch.ys2[nn][0];
            const ulonglong2 yB = *(const ulonglong2*)&smb.ch.ys2[nn][4];
            float ul[4], uh[4];
#pragma unroll
            for (int g = 0; g < 4; g++) {
                u64t v = fma2(sx2[g], yA.x, hs2[g]);
                v = fma2(sy2[g], yA.y, v);
                v = fma2(sz2[g], yB.x, v);
                v = add2(v, yB.y);
                upk2(ul[g], uh[g], v);
                mBlo[g] = fmaxf(mBlo[g], ul[g]);
                mBhi[g] = fmaxf(mBhi[g], uh[g]);
            }
            smb.ch.mred[k][tid] = fmaxf(fmaxf(fmaxf(ul[0], uh[0]), fmaxf(ul[1], uh[1])),
                                        fmaxf(fmaxf(ul[2], uh[2]), fmaxf(ul[3], uh[3])));
        }
        __syncthreads();
        {
            const int nnl = tid & 31, part = tid >> 5;
            const float* row = &smb.ch.mred[nnl][part * 32];
            float sm = row[0];
#pragma unroll
            for (int j = 1; j < 32; j++) sm = fmaxf(sm, row[j]);
            smb.ch.pw2[nnl][part] = sm;
        }
        __syncthreads();
        if (tid < 32)
            sum_n += fmaxf(fmaxf(smb.ch.pw2[tid][0], smb.ch.pw2[tid][1]),
                           fmaxf(smb.ch.pw2[tid][2], smb.ch.pw2[tid][3]));
        __syncthreads();
    }

    if (tid < 32) {
#pragma unroll
        for (int off = 16; off; off >>= 1)
            sum_n += __shfl_xor_sync(0xffffffffu, sum_n, off);
        if (tid == 0) g_partN[bid] = sum_n;
    }

#pragma unroll
    for (int g = 0; g < 4; g++) {
        const int m0 = w * 256 + (2 * g) * 32 + lane;
        atomicMax(&g_umax[b * 1024 + m0],      enc_f(mBlo[g]));
        atomicMax(&g_umax[b * 1024 + m0 + 32], enc_f(mBhi[g]));
    }

    __threadfence();
    __syncthreads();
    if (tid == 0) isLast = (atomicAdd(&g_done, 1u) == 511u) ? 1u : 0u;
    __syncthreads();
    if (isLast) {
        float loc = 0.f;
        for (int i = tid; i < 2048; i += 128) loc += dec_f(g_umax[i]);
        for (int i = tid; i < 512; i += 128)  loc += g_partN[i];
#pragma unroll
        for (int off = 16; off; off >>= 1)
            loc += __shfl_xor_sync(0xffffffffu, loc, off);
        if (lane == 0) smb.ch.red2[w] = loc;
        __syncthreads();
        if (tid == 0)
            out[0] = -2.f * ((smb.ch.red2[0] + smb.ch.red2[1]) +
                             (smb.ch.red2[2] + smb.ch.red2[3]));
    }
}

// ---------------------------------------------------------------------------
extern "C" void kernel_launch(void* const* d_in, const int* in_sizes, int n_in,
                              void* d_out, int out_size) {
    const float* x    = (const float*)d_in[0];
    const float* grid = (const float*)d_in[1];
    const float* We1  = (const float*)d_in[2];
    const float* be1  = (const float*)d_in[3];
    const float* We2  = (const float*)d_in[4];
    const float* be2  = (const float*)d_in[5];
    const float* We3  = (const float*)d_in[6];
    const float* be3  = (const float*)d_in[7];
    const float* Wd1  = (const float*)d_in[8];
    const float* bd1  = (const float*)d_in[9];
    const float* Wd2  = (const float*)d_in[10];
    const float* bd2  = (const float*)d_in[11];
    const float* Wd3  = (const float*)d_in[12];
    const float* bd3  = (const float*)d_in[13];
    float* out = (float*)d_out;

    k_enc<<<128, 128>>>(x, We1, be1, We2, be2, We3, be3, grid, Wd1, bd1, Wd2, bd2);
    k_decch<<<768, 128>>>(Wd3, bd3, x, out);
}

// round 17
// speedup vs baseline: 1.1107x; 1.1107x over previous
#include <cuda_runtime.h>
#include <cuda_bf16.h>
#include <math.h>

// ---------------------------------------------------------------------------
// AutoEncoder3D + symmetric Chamfer loss.
// 3-kernel pipeline: fused encoder (global-barrier, 128 co-resident blocks),
// dec3 GEMM (768 blocks), fused tanh+chamfer (512 blocks, last-block reduce).
// B=2, D_IN=1024, SPACE=3, BOTT=64, G=64, N=G*1024=65536 per batch.
// ---------------------------------------------------------------------------

#define NEG_INF (__int_as_float(0xff800000))

typedef unsigned long long u64t;
__device__ __forceinline__ u64t pk2(float lo, float hi) {
    u64t r; asm("mov.b64 %0, {%1, %2};" : "=l"(r) : "f"(lo), "f"(hi)); return r;
}
__device__ __forceinline__ void upk2(float& lo, float& hi, u64t v) {
    asm("mov.b64 {%0, %1}, %2;" : "=f"(lo), "=f"(hi) : "l"(v));
}
__device__ __forceinline__ u64t fma2(u64t a, u64t b, u64t c) {
    u64t d; asm("fma.rn.f32x2 %0, %1, %2, %3;" : "=l"(d) : "l"(a), "l"(b), "l"(c)); return d;
}
__device__ __forceinline__ u64t add2(u64t a, u64t b) {
    u64t d; asm("add.rn.f32x2 %0, %1, %2;" : "=l"(d) : "l"(a), "l"(b)); return d;
}

// ---------------- scratch ----------------------------------------------------
__device__ float    g_h1part[16][2][512];
__device__ float    g_h2part[8][2][128];
__device__ float    g_d2t[512 * 128];        // dec L2 activations, transposed [k][row]
__device__ float    g_p3[8][128 * 3072];     // dec3 K-split partials
__device__ unsigned g_umax[2048];
__device__ float    g_partN[512];
__device__ unsigned g_done;
__device__ unsigned g_barA1, g_barA2;        // k_enc barrier counters

__device__ __forceinline__ unsigned enc_f(float f) {
    unsigned u = __float_as_uint(f);
    return (u & 0x80000000u) ? ~u : (u | 0x80000000u);
}
__device__ __forceinline__ float dec_f(unsigned u) {
    unsigned v = (u & 0x80000000u) ? (u & 0x7FFFFFFFu) : ~u;
    return __uint_as_float(v);
}

// counter global barrier; safe iff the whole grid is co-resident
__device__ __forceinline__ void gbar(unsigned* ctr, unsigned target) {
    __syncthreads();
    __threadfence();
    if (threadIdx.x == 0) {
        atomicAdd(ctr, 1u);
        while (*((volatile unsigned*)ctr) < target) {}
    }
    __syncthreads();
    __threadfence();
}

// ============================================================================
// Kernel A: encoder L1 (K-split x16) + L2 (K-split x8) + e3/dec12
// Grid 128 x 128 threads. 128 <= 148 SMs -> always co-resident.
// ============================================================================
__global__ void __launch_bounds__(128) k_enc(
    const float* __restrict__ x, const float* __restrict__ We1,
    const float* __restrict__ be1, const float* __restrict__ We2,
    const float* __restrict__ be2, const float* __restrict__ We3,
    const float* __restrict__ be3, const float* __restrict__ grid,
    const float* __restrict__ Wd1, const float* __restrict__ bd1,
    const float* __restrict__ Wd2, const float* __restrict__ bd2)
{
    __shared__ float sm[256];                    // xs(192) / h1c(64) / reused
    __shared__ float d1s[128];
    const int tid = threadIdx.x, bid = blockIdx.x;

    if (bid == 0) {                              // per-replay re-init
        for (int i = tid; i < 2048; i += 128) g_umax[i] = 0u;
        if (tid == 0) g_done = 0u;
    }

    // ---- phase 1: e1. 128 blocks = 32 (b,kc) pairs x 4 col-chunks ----------
    {
        const int pair = bid >> 2, chunk = bid & 3;
        const int b = pair >> 4, kc = pair & 15;
        const int col = chunk * 128 + tid;
        for (int i = tid; i < 192; i += 128) sm[i] = x[b * 3072 + kc * 192 + i];
        __syncthreads();
        const float* W = We1 + (size_t)(kc * 192) * 512 + col;
        float a0 = 0.f, a1 = 0.f, a2 = 0.f, a3 = 0.f;
#pragma unroll 16
        for (int i = 0; i < 192; i += 4) {
            a0 = fmaf(sm[i + 0], W[(size_t)(i + 0) * 512], a0);
            a1 = fmaf(sm[i + 1], W[(size_t)(i + 1) * 512], a1);
            a2 = fmaf(sm[i + 2], W[(size_t)(i + 2) * 512], a2);
            a3 = fmaf(sm[i + 3], W[(size_t)(i + 3) * 512], a3);
        }
        g_h1part[kc][b][col] = (a0 + a1) + (a2 + a3);
    }
    gbar(&g_barA1, 128);

    // ---- phase 2: e2 on blocks 0..15 ---------------------------------------
    if (bid < 16) {
        const int b = bid >> 3, kc = bid & 7;
        if (tid < 64) {
            const int col = kc * 64 + tid;
            float a = be1[col];
#pragma unroll
            for (int p = 0; p < 16; p++) a += g_h1part[p][b][col];
            sm[tid] = fmaxf(a, 0.f);
        }
        __syncthreads();
        const float* W = We2 + (size_t)(kc * 64) * 128 + tid;
        float c0 = 0.f, c1 = 0.f, c2 = 0.f, c3 = 0.f;
#pragma unroll
        for (int k = 0; k < 64; k += 4) {
            c0 = fmaf(sm[k + 0], W[(size_t)(k + 0) * 128], c0);
            c1 = fmaf(sm[k + 1], W[(size_t)(k + 1) * 128], c1);
            c2 = fmaf(sm[k + 2], W[(size_t)(k + 2) * 128], c2);
            c3 = fmaf(sm[k + 3], W[(size_t)(k + 3) * 128], c3);
        }
        g_h2part[kc][b][tid] = (c0 + c1) + (c2 + c3);
    }
    gbar(&g_barA2, 128);

    // ---- phase 3: e3 + dec layers 1+2, one block per (b,g) -----------------
    {
        const int r = bid, b = r >> 6, g = r & 63;
        float* h2s = sm;                          // reuse [0..127]
        float* zi  = sm + 128;                    // [128..195] (68 used)
        {
            float a = be2[tid];
#pragma unroll
            for (int p = 0; p < 8; p++) a += g_h2part[p][b][tid];
            h2s[tid] = fmaxf(a, 0.f);
        }
        __syncthreads();
        if (tid < 64) {
            float a = be3[tid];
#pragma unroll 8
            for (int i = 0; i < 128; i++) a = fmaf(h2s[i], We3[(size_t)i * 64 + tid], a);
            zi[tid] = fmaxf(a, 0.f);
        } else if (tid < 67) {
            zi[tid] = grid[g * 3 + (tid - 64)];
        }
        __syncthreads();

        float a = bd1[tid];
#pragma unroll
        for (int i = 0; i < 67; i++) a = fmaf(zi[i], Wd1[(size_t)i * 128 + tid], a);
        d1s[tid] = fmaxf(a, 0.f);
        __syncthreads();

        float c0 = bd2[tid], c1 = bd2[tid + 128], c2 = bd2[tid + 256], c3 = bd2[tid + 384];
#pragma unroll 8
        for (int i = 0; i < 128; i++) {
            const float h = d1s[i];
            const float* W = Wd2 + (size_t)i * 512 + tid;
            c0 = fmaf(h, W[0],   c0);
            c1 = fmaf(h, W[128], c1);
            c2 = fmaf(h, W[256], c2);
            c3 = fmaf(h, W[384], c3);
        }
        g_d2t[(size_t)(tid)       * 128 + r] = fmaxf(c0, 0.f);
        g_d2t[(size_t)(tid + 128) * 128 + r] = fmaxf(c1, 0.f);
        g_d2t[(size_t)(tid + 256) * 128 + r] = fmaxf(c2, 0.f);
        g_d2t[(size_t)(tid + 384) * 128 + r] = fmaxf(c3, 0.f);
    }
}

// ============================================================================
// Kernel B: dec3 — 128x3072x512 GEMM, 8-way K-split (R12-measured: 15.1 us)
// Grid: 768 = 96 n-tiles x 8 K-chunks of 64. Block: 128 threads.
// Row-pair FFMA2 accumulators; 3 LDS.128 + 4 pk2 + 16 FFMA2 per kk.
// ============================================================================
__global__ void k_dec3(const float* __restrict__ Wd3) {
    __shared__ __align__(16) float As[16][132];   // [kk][row]
    __shared__ __align__(16) float Bs[16][32];    // [kk][col]
    const int tid = threadIdx.x;                  // 128
    const int nt = blockIdx.x % 96, kc = blockIdx.x / 96;
    const int n0 = nt * 32, kbase = kc * 64;
    const int tx = tid & 7, ty = tid >> 3;

    u64t acc[4][4];
#pragma unroll
    for (int p = 0; p < 4; p++)
#pragma unroll
        for (int c = 0; c < 4; c++) acc[p][c] = 0ull;

    const int kkA = tid >> 5, r4 = tid & 31;
    const int kkB = tid >> 3, c4 = tid & 7;

    for (int ks = 0; ks < 64; ks += 16) {
#pragma unroll
        for (int j = 0; j < 4; j++) {
            const int kk = kkA + j * 4;
            *(float4*)&As[kk][r4 * 4] =
                *(const float4*)&g_d2t[(size_t)(kbase + ks + kk) * 128 + r4 * 4];
        }
        *(float4*)&Bs[kkB][c4 * 4] =
            *(const float4*)&Wd3[(size_t)(kbase + ks + kkB) * 3072 + n0 + c4 * 4];
        __syncthreads();
#pragma unroll
        for (int kk = 0; kk < 16; kk++) {
            const ulonglong2 aA = *(const ulonglong2*)&As[kk][ty * 8];
            const ulonglong2 aB = *(const ulonglong2*)&As[kk][ty * 8 + 4];
            const float4 bv = *(const float4*)&Bs[kk][tx * 4];
            const u64t b0 = pk2(bv.x, bv.x), b1 = pk2(bv.y, bv.y);
            const u64t b2 = pk2(bv.z, bv.z), b3 = pk2(bv.w, bv.w);
            acc[0][0] = fma2(aA.x, b0, acc[0][0]); acc[0][1] = fma2(aA.x, b1, acc[0][1]);
            acc[0][2] = fma2(aA.x, b2, acc[0][2]); acc[0][3] = fma2(aA.x, b3, acc[0][3]);
            acc[1][0] = fma2(aA.y, b0, acc[1][0]); acc[1][1] = fma2(aA.y, b1, acc[1][1]);
            acc[1][2] = fma2(aA.y, b2, acc[1][2]); acc[1][3] = fma2(aA.y, b3, acc[1][3]);
            acc[2][0] = fma2(aB.x, b0, acc[2][0]); acc[2][1] = fma2(aB.x, b1, acc[2][1]);
            acc[2][2] = fma2(aB.x, b2, acc[2][2]); acc[2][3] = fma2(aB.x, b3, acc[2][3]);
            acc[3][0] = fma2(aB.y, b0, acc[3][0]); acc[3][1] = fma2(aB.y, b1, acc[3][1]);
            acc[3][2] = fma2(aB.y, b2, acc[3][2]); acc[3][3] = fma2(aB.y, b3, acc[3][3]);
        }
        __syncthreads();
    }

    float* P = g_p3[kc];
#pragma unroll
    for (int p = 0; p < 4; p++) {
        float l0, h0, l1, h1, l2, h2, l3, h3;
        upk2(l0, h0, acc[p][0]);
        upk2(l1, h1, acc[p][1]);
        upk2(l2, h2, acc[p][2]);
        upk2(l3, h3, acc[p][3]);
        const int r0 = ty * 8 + 2 * p;
        *(float4*)&P[(size_t)r0 * 3072 + n0 + tx * 4]       = make_float4(l0, l1, l2, l3);
        *(float4*)&P[(size_t)(r0 + 1) * 3072 + n0 + tx * 4] = make_float4(h0, h1, h2, h3);
    }
}

// ============================================================================
// Kernel C: fused partial-sum + bias + tanh + symmetric Chamfer + final reduce
// u = s.y - 0.5|s|^2 - 0.5|y|^2  =>  min d2 = -2 * max u, both directions.
// ============================================================================
#define CH_NS 256
__global__ void k_chamfer(const float* __restrict__ x, const float* __restrict__ bd3,
                          float* __restrict__ out) {
    __shared__ __align__(16) float ys2[CH_NS][8]; // {yx,yx,yy,yy,yz,yz,yw,yw}
    __shared__ __align__(16) float ysc[CH_NS * 3];
    __shared__ float mred[32][133];
    __shared__ float pw2[32][4];
    __shared__ float red2[4];
    __shared__ unsigned isLast;
    const int tid  = threadIdx.x;                 // 128
    const int lane = tid & 31, w = tid >> 5;
    const int bidx = blockIdx.x;                  // 512 blocks
    const int b = bidx >> 8, s = bidx & 255;
    const int n0 = s * CH_NS;

    if (bidx == 511 && tid == 0) { g_barA1 = 0u; g_barA2 = 0u; }  // next replay

    // --- phase 1: Y = tanh(sum of 8 K-split partials + bias), 256 points ----
    {
        const int gf0 = b * 196608 + n0 * 3;
        const int col0 = (n0 & 1023) * 3;
        for (int o4 = tid; o4 < 192; o4 += 128) {
            const int o = o4 * 4;
            float4 sacc = *(const float4*)&g_p3[0][gf0 + o];
#pragma unroll
            for (int p = 1; p < 8; p++) {
                const float4 q = *(const float4*)&g_p3[p][gf0 + o];
                sacc.x += q.x; sacc.y += q.y; sacc.z += q.z; sacc.w += q.w;
            }
            const float4 bb = *(const float4*)&bd3[col0 + o];
            sacc.x = tanhf(sacc.x + bb.x);
            sacc.y = tanhf(sacc.y + bb.y);
            sacc.z = tanhf(sacc.z + bb.z);
            sacc.w = tanhf(sacc.w + bb.w);
            *(float4*)&ysc[o] = sacc;
        }
    }
    __syncthreads();
    for (int nn = tid; nn < CH_NS; nn += 128) {
        const float yx = ysc[nn * 3 + 0];
        const float yy = ysc[nn * 3 + 1];
        const float yz = ysc[nn * 3 + 2];
        const float yw = -0.5f * (yx * yx + yy * yy + yz * yz);
        *(float4*)&ys2[nn][0] = make_float4(yx, yx, yy, yy);
        *(float4*)&ys2[nn][4] = make_float4(yz, yz, yw, yw);
    }

    // --- phase 2: per-lane targets, 8 m's as 4 packed pairs ------------------
    u64t sx2[4], sy2[4], sz2[4], hs2[4];
    float mBlo[4], mBhi[4];
    const float* xb = x + (size_t)b * 3072;
#pragma unroll
    for (int g = 0; g < 4; g++) {
        const int m0 = w * 256 + (2 * g) * 32 + lane;
        const int m1 = m0 + 32;
        const float ax = xb[m0 * 3 + 0], ay = xb[m0 * 3 + 1], az = xb[m0 * 3 + 2];
        const float cx = xb[m1 * 3 + 0], cy = xb[m1 * 3 + 1], cz = xb[m1 * 3 + 2];
        sx2[g] = pk2(ax, cx);
        sy2[g] = pk2(ay, cy);
        sz2[g] = pk2(az, cz);
        hs2[g] = pk2(-0.5f * (ax * ax + ay * ay + az * az),
                     -0.5f * (cx * cx + cy * cy + cz * cz));
        mBlo[g] = NEG_INF; mBhi[g] = NEG_INF;
    }
    __syncthreads();

    float sum_n = 0.f;                            // meaningful for tid < 32
    for (int c0 = 0; c0 < CH_NS; c0 += 32) {
#pragma unroll 2
        for (int k = 0; k < 32; k++) {
            const int nn = c0 + k;
            const ulonglong2 yA = *(const ulonglong2*)&ys2[nn][0];
            const ulonglong2 yB = *(const ulonglong2*)&ys2[nn][4];
            float ul[4], uh[4];
#pragma unroll
            for (int g = 0; g < 4; g++) {
                u64t v = fma2(sx2[g], yA.x, hs2[g]);
                v = fma2(sy2[g], yA.y, v);
                v = fma2(sz2[g], yB.x, v);
                v = add2(v, yB.y);
                upk2(ul[g], uh[g], v);
                mBlo[g] = fmaxf(mBlo[g], ul[g]);
                mBhi[g] = fmaxf(mBhi[g], uh[g]);
            }
            mred[k][tid] = fmaxf(fmaxf(fmaxf(ul[0], uh[0]), fmaxf(ul[1], uh[1])),
                                 fmaxf(fmaxf(ul[2], uh[2]), fmaxf(ul[3], uh[3])));
        }
        __syncthreads();
        {
            const int nnl = tid & 31, part = tid >> 5;
            const float* row = &mred[nnl][part * 32];
            float sm = row[0];
#pragma unroll
            for (int j = 1; j < 32; j++) sm = fmaxf(sm, row[j]);
            pw2[nnl][part] = sm;
        }
        __syncthreads();
        if (tid < 32)
            sum_n += fmaxf(fmaxf(pw2[tid][0], pw2[tid][1]),
                           fmaxf(pw2[tid][2], pw2[tid][3]));
        __syncthreads();
    }

    if (tid < 32) {
#pragma unroll
        for (int off = 16; off; off >>= 1)
            sum_n += __shfl_xor_sync(0xffffffffu, sum_n, off);
        if (tid == 0) g_partN[bidx] = sum_n;
    }

#pragma unroll
    for (int g = 0; g < 4; g++) {
        const int m0 = w * 256 + (2 * g) * 32 + lane;
        atomicMax(&g_umax[b * 1024 + m0],      enc_f(mBlo[g]));
        atomicMax(&g_umax[b * 1024 + m0 + 32], enc_f(mBhi[g]));
    }

    // --- last-block final reduction -----------------------------------------
    __threadfence();
    __syncthreads();
    if (tid == 0) isLast = (atomicAdd(&g_done, 1u) == 511u) ? 1u : 0u;
    __syncthreads();
    if (isLast) {
        float loc = 0.f;
        for (int i = tid; i < 2048; i += 128) loc += dec_f(g_umax[i]);
        for (int i = tid; i < 512; i += 128)  loc += g_partN[i];
#pragma unroll
        for (int off = 16; off; off >>= 1)
            loc += __shfl_xor_sync(0xffffffffu, loc, off);
        if (lane == 0) red2[w] = loc;
        __syncthreads();
        if (tid == 0)
            out[0] = -2.f * ((red2[0] + red2[1]) + (red2[2] + red2[3]));
    }
}

// ---------------------------------------------------------------------------
extern "C" void kernel_launch(void* const* d_in, const int* in_sizes, int n_in,
                              void* d_out, int out_size) {
    const float* x    = (const float*)d_in[0];
    const float* grid = (const float*)d_in[1];
    const float* We1  = (const float*)d_in[2];
    const float* be1  = (const float*)d_in[3];
    const float* We2  = (const float*)d_in[4];
    const float* be2  = (const float*)d_in[5];
    const float* We3  = (const float*)d_in[6];
    const float* be3  = (const float*)d_in[7];
    const float* Wd1  = (const float*)d_in[8];
    const float* bd1  = (const float*)d_in[9];
    const float* Wd2  = (const float*)d_in[10];
    const float* bd2  = (const float*)d_in[11];
    const float* Wd3  = (const float*)d_in[12];
    const float* bd3  = (const float*)d_in[13];
    float* out = (float*)d_out;

    k_enc<<<128, 128>>>(x, We1, be1, We2, be2, We3, be3, grid, Wd1, bd1, Wd2, bd2);
    k_dec3<<<768, 128>>>(Wd3);
    k_chamfer<<<512, 128>>>(x, bd3, out);
}